// round 16
// baseline (speedup 1.0000x reference)
#include <cuda_runtime.h>
#include <math_constants.h>

#define NB      32
#define NC      3
#define HH      512
#define WW      512
#define NPATCH  4
#define PSZ     128
#define HALF    64
#define MARGIN  32

typedef unsigned long long u64;

// Scratch (__device__ globals; allocs forbidden)
__device__ u64 g_rowkey[NB * HH];           // packed (valbits<<32)|~flatidx per row
__device__ int g_coords[NB * NPATCH * 2];   // (x1, y1) per (b, n)

__device__ __forceinline__ u64 umax64(u64 a, u64 b) { return a > b ? a : b; }

// Reduce one row's 16 per-lane values to a packed argmax key (valid on all lanes).
// Values are >= 0 (uniform [0,1)) so float-bit order == value order; ~flat gives
// first-occurrence tie-break under unsigned max.
__device__ __forceinline__ u64 row_reduce(const float v[16], int lane, int y) {
    float m8[8], m4[4], m;
    #pragma unroll
    for (int i = 0; i < 8; i++) m8[i] = fmaxf(v[i], v[i + 8]);
    #pragma unroll
    for (int i = 0; i < 4; i++) m4[i] = fmaxf(m8[i], m8[i + 4]);
    m = fmaxf(fmaxf(m4[0], m4[2]), fmaxf(m4[1], m4[3]));
    #pragma unroll
    for (int o = 16; o; o >>= 1) m = fmaxf(m, __shfl_xor_sync(0xffffffffu, m, o));

    int lmin = 0x7fffffff;
    #pragma unroll
    for (int i = 0; i < 4; i++)
        #pragma unroll
        for (int q = 0; q < 4; q++)
            if (v[i * 4 + q] == m) lmin = min(lmin, (lane + i * 32) * 4 + q);
    #pragma unroll
    for (int o = 16; o; o >>= 1) lmin = min(lmin, __shfl_xor_sync(0xffffffffu, lmin, o));

    if (m < 0.0f) return 0ull;   // fully-masked row
    return ((u64)__float_as_uint(m) << 32) | (unsigned)(~(y * WW + lmin));
}

// ---------------------------------------------------------------------------
// Kernel A: per-row packed argmax keys. One warp per TWO rows, loads batched
// first (8 independent LDG.128 per lane -> MLP 8) then reduced.
// ---------------------------------------------------------------------------
__global__ void rowkey_init(const float* __restrict__ umap) {
    int w    = blockIdx.x * 8 + (threadIdx.x >> 5);   // warp id, 8192 total
    int lane = threadIdx.x & 31;
    int row0 = w * 2;                                  // global row (b*512 + y)

    const float4* r0 = (const float4*)(umap + (size_t)row0 * WW);
    const float4* r1 = (const float4*)(umap + (size_t)(row0 + 1) * WW);
    float4 A[4], B[4];
    #pragma unroll
    for (int i = 0; i < 4; i++) A[i] = r0[lane + i * 32];
    #pragma unroll
    for (int i = 0; i < 4; i++) B[i] = r1[lane + i * 32];

    float va[16], vb[16];
    #pragma unroll
    for (int i = 0; i < 4; i++) {
        va[i*4+0]=A[i].x; va[i*4+1]=A[i].y; va[i*4+2]=A[i].z; va[i*4+3]=A[i].w;
        vb[i*4+0]=B[i].x; vb[i*4+1]=B[i].y; vb[i*4+2]=B[i].z; vb[i*4+3]=B[i].w;
    }
    u64 k0 = row_reduce(va, lane, row0 & 511);
    u64 k1 = row_reduce(vb, lane, (row0 + 1) & 511);
    if (lane == 0) {
        g_rowkey[row0]     = k0;
        g_rowkey[row0 + 1] = k1;
    }
}

// ---------------------------------------------------------------------------
// Fused greedy selection: one cluster of 4 CTAs (512 thr each) per batch.
// All 4 picks + 3 band rescans in a single kernel; cross-CTA ordering via
// barrier.cluster (release/acquire) and L2-scoped key accesses (ldcg/stcg).
// Every CTA redundantly computes the pick (identical result, deterministic).
// ---------------------------------------------------------------------------
__global__ void __cluster_dims__(4, 1, 1) __launch_bounds__(512, 1)
steps_kernel(const float* __restrict__ umap, float* __restrict__ coords_out) {
    int rank = blockIdx.x & 3;
    int b    = blockIdx.x >> 2;
    int t    = threadIdx.x;
    int w    = t >> 5, lane = t & 31;

    __shared__ u64 sred[16];
    __shared__ int sbox[NPATCH][4];
    __shared__ int sband[2];

    u64* keys = g_rowkey + b * HH;
    const float* um = umap + (size_t)b * HH * WW;

    for (int step = 0; step < NPATCH; step++) {
        // ---- argmax over 512 row keys (L2-scoped loads; all CTAs identical) ----
        u64 k = __ldcg(&keys[t]);
        #pragma unroll
        for (int o = 16; o; o >>= 1) k = umax64(k, __shfl_xor_sync(0xffffffffu, k, o));
        if (lane == 0) sred[w] = k;
        __syncthreads();
        if (t == 0) {
            u64 best = sred[0];
            #pragma unroll
            for (int i = 1; i < 16; i++) best = umax64(best, sred[i]);
            unsigned flat = ~(unsigned)best;
            int yc = (flat >> 9) & 511;
            int xc = flat & 511;
            int x1 = min(max(xc - HALF, 0), WW - PSZ);
            int y1 = min(max(yc - HALF, 0), HH - PSZ);
            sbox[step][0] = x1 - MARGIN;       sbox[step][1] = y1 - MARGIN;
            sbox[step][2] = x1 + PSZ + MARGIN; sbox[step][3] = y1 + PSZ + MARGIN;
            sband[0] = max(y1 - MARGIN, 0);
            sband[1] = min(y1 + PSZ + MARGIN, HH);
            if (rank == 0) {
                g_coords[(b * NPATCH + step) * 2 + 0] = x1;
                g_coords[(b * NPATCH + step) * 2 + 1] = y1;
                int co = (b * NPATCH + step) * 4;
                coords_out[co + 0] = (float)x1;
                coords_out[co + 1] = (float)y1;
                coords_out[co + 2] = (float)(x1 + PSZ);
                coords_out[co + 3] = (float)(y1 + PSZ);
            }
        }
        __syncthreads();
        if (step == NPATCH - 1) break;

        // ---- rescan suppression band: 64 cluster-warps over <=192 rows ----
        int y1c = sband[0];
        int nrows = sband[1] - y1c;
        int gw = rank * 16 + w;
        for (int j = gw; j < nrows; j += 64) {
            int y = y1c + j;
            bool yh[NPATCH];
            #pragma unroll
            for (int kk = 0; kk < NPATCH; kk++)
                yh[kk] = (kk <= step) && (y >= sbox[kk][1]) && (y < sbox[kk][3]);

            const float4* rp = (const float4*)(um + (size_t)y * WW);
            float v[16];
            #pragma unroll
            for (int i = 0; i < 4; i++) {
                float4 f = rp[lane + i * 32];
                float e[4] = {f.x, f.y, f.z, f.w};
                #pragma unroll
                for (int q = 0; q < 4; q++) {
                    int x = (lane + i * 32) * 4 + q;
                    bool msk = false;
                    #pragma unroll
                    for (int kk = 0; kk < NPATCH; kk++)
                        msk = msk || (yh[kk] && x >= sbox[kk][0] && x < sbox[kk][2]);
                    v[i * 4 + q] = msk ? -CUDART_INF_F : e[q];
                }
            }
            u64 nk = row_reduce(v, lane, y);
            if (lane == 0) __stcg(&keys[y], nk);
        }

        // ---- cluster barrier: release stcg writes, acquire for next pick ----
        asm volatile("barrier.cluster.arrive.aligned;" ::: "memory");
        asm volatile("barrier.cluster.wait.aligned;"   ::: "memory");
    }
}

// ---------------------------------------------------------------------------
// Extract: 2 CTAs per (b, n, c), 64 patch rows each. Coalesced 512B rows.
// ---------------------------------------------------------------------------
__global__ void extract_patches(const float* __restrict__ images,
                                float* __restrict__ out) {
    int bid  = blockIdx.x;
    int half = bid & 1;
    int idx  = bid >> 1;
    int b    = idx / (NPATCH * NC);
    int rem  = idx % (NPATCH * NC);
    int n    = rem / NC;
    int c    = rem % NC;

    int x1 = g_coords[(b * NPATCH + n) * 2 + 0];
    int y1 = g_coords[(b * NPATCH + n) * 2 + 1] + half * 64;

    const float* src = images + (((size_t)b * NC + c) * HH + y1) * WW + x1;
    float4* dst = (float4*)(out + ((size_t)(b * NPATCH + n) * NC + c) * PSZ * PSZ)
                  + half * (64 * PSZ / 4);

    const int n4 = 64 * PSZ / 4;   // 2048 float4
    if ((x1 & 3) == 0) {
        const float4* sp = (const float4*)src;
        for (int i = threadIdx.x; i < n4; i += 256) {
            int row  = i >> 5;
            int col4 = i & 31;
            dst[i] = sp[row * (WW / 4) + col4];
        }
    } else {
        for (int i = threadIdx.x; i < n4; i += 256) {
            int row = i >> 5;
            int col = (i & 31) * 4;
            const float* s = src + row * WW + col;
            dst[i] = make_float4(s[0], s[1], s[2], s[3]);
        }
    }
}

// ---------------------------------------------------------------------------
extern "C" void kernel_launch(void* const* d_in, const int* in_sizes, int n_in,
                              void* d_out, int out_size) {
    const float* images = (const float*)d_in[0];
    const float* umaps  = (const float*)d_in[1];
    if (n_in >= 2 && in_sizes[0] < in_sizes[1]) {
        images = (const float*)d_in[1];
        umaps  = (const float*)d_in[0];
    }

    float* patches = (float*)d_out;
    float* coords  = (float*)d_out + (out_size - NB * NPATCH * 4);

    rowkey_init    <<<NB * HH / 16, 256>>>(umaps);           // 1024 CTAs, 2 rows/warp
    steps_kernel   <<<NB * 4, 512>>>(umaps, coords);         // 32 clusters of 4 CTAs
    extract_patches<<<NB * NPATCH * NC * 2, 256>>>(images, patches);
}